// round 1
// baseline (speedup 1.0000x reference)
#include <cuda_runtime.h>
#include <cstdint>

#define TWO_PI_F 6.283185307179586f
#define S_TOTAL 1024
#define Dm 96
#define Din 64
#define NBg 8
#define Bsz 8
#define WELEM (Dm * Dm)          // 9216
#define CHUNK 128
#define SMEM_FLOATS 42208
#define SMEM_BYTES (SMEM_FLOATS * 4)

// Scratch: per-position weight matrices, layout W[s][j][i] (i contiguous)
__device__ float g_W1[(size_t)S_TOTAL * WELEM];
__device__ float g_W2[(size_t)S_TOTAL * WELEM];

__device__ __forceinline__ void cp_async16(void* dst, const void* src) {
    unsigned d = (unsigned)__cvta_generic_to_shared(dst);
    asm volatile("cp.async.cg.shared.global [%0], [%1], 16;\n" :: "r"(d), "l"(src));
}

__device__ __forceinline__ float warp_sum(float v) {
    v += __shfl_xor_sync(0xffffffffu, v, 16);
    v += __shfl_xor_sync(0xffffffffu, v, 8);
    v += __shfl_xor_sync(0xffffffffu, v, 4);
    v += __shfl_xor_sync(0xffffffffu, v, 2);
    v += __shfl_xor_sync(0xffffffffu, v, 1);
    return v;
}

// ---------------------------------------------------------------------------
// Kernel 1: build W[s,i,j] = sum_g P[i,j,g] * cos(2*pi*s / T),
//           T = (i*96+j)*8 + g + 2, via Chebyshev recurrence
//           c_{s+1} = 2*cos(2pi/T)*c_s - c_{s-1}, refreshed every CHUNK steps.
// grid: (9216/256, 1024/CHUNK, 2), block: 256
// Thread e -> (i = e%96, j = e/96); stores to s*9216 + e  (coalesced 128B/warp).
// ---------------------------------------------------------------------------
__global__ void __launch_bounds__(256) precompute_W(const float* __restrict__ P1,
                                                    const float* __restrict__ P2) {
    const int e = blockIdx.x * 256 + threadIdx.x;       // 0..9215
    const float* __restrict__ P = blockIdx.z ? P2 : P1;
    float* __restrict__ Wg = blockIdx.z ? g_W2 : g_W1;
    const int i = e % Dm;
    const int j = e / Dm;
    const int base = (i * Dm + j) * NBg;
    const int s0 = blockIdx.y * CHUNK;

    float p[NBg], a2[NBg], c[NBg], cp[NBg];
#pragma unroll
    for (int g = 0; g < NBg; g++) {
        float T = (float)(base + g + 2);
        float invT = 1.0f / T;
        a2[g] = 2.0f * cosf(TWO_PI_F * invT);
        c[g]  = cosf(TWO_PI_F * (fmodf((float)s0, T) * invT));
        cp[g] = cosf(TWO_PI_F * (fmodf((float)(s0 - 1), T) * invT));
        p[g]  = P[base + g];
    }

    float* __restrict__ outp = Wg + (size_t)s0 * WELEM + e;
#pragma unroll 4
    for (int s = 0; s < CHUNK; s++) {
        float w = 0.0f;
#pragma unroll
        for (int g = 0; g < NBg; g++) w = fmaf(p[g], c[g], w);
        outp[(size_t)s * WELEM] = w;
#pragma unroll
        for (int g = 0; g < NBg; g++) {
            float cn = fmaf(a2[g], c[g], -cp[g]);
            cp[g] = c[g];
            c[g] = cn;
        }
    }
}

// ---------------------------------------------------------------------------
// Kernel 2: fused layer1 + layer2 for one position s per block.
// block = 256 threads = 8 warps; warp b handles batch b; lane owns
// i in {lane, lane+32, lane+64}. W1/W2 prefetched to smem via cp.async;
// M1^T / Wres1^T / M2^T staged with pad-97 rows (conflict-free LDS).
// ---------------------------------------------------------------------------
__global__ void __launch_bounds__(256) layers_kernel(
    const float* __restrict__ seq,
    const float* __restrict__ M1,
    const float* __restrict__ Wres1,
    const float* __restrict__ g1v, const float* __restrict__ b1v,
    const float* __restrict__ M2,
    const float* __restrict__ g2v, const float* __restrict__ b2v,
    float* __restrict__ out)
{
    extern __shared__ float sm[];
    float* sW1  = sm;                // 9216
    float* sW2  = sm + 9216;         // 9216
    float* sM1T = sm + 18432;        // 64*97 = 6208
    float* sWrT = sm + 24640;        // 6208
    float* sM2T = sm + 30848;        // 96*97 = 9312
    float* sx   = sm + 40160;        // 8*64  = 512
    float* sxn  = sm + 40672;        // 8*96  = 768
    float* sx1  = sm + 41440;        // 8*96  = 768

    const int s = blockIdx.x;
    const int tid = threadIdx.x;
    const int b = tid >> 5;
    const int lane = tid & 31;

    // --- async prefetch of W1 (group A) then W2 (group B) ---
    {
        const float4* src1 = (const float4*)(g_W1 + (size_t)s * WELEM);
        float4* dst1 = (float4*)sW1;
#pragma unroll
        for (int t = 0; t < 9; t++) cp_async16(dst1 + tid + t * 256, src1 + tid + t * 256);
        asm volatile("cp.async.commit_group;\n");
        const float4* src2 = (const float4*)(g_W2 + (size_t)s * WELEM);
        float4* dst2 = (float4*)sW2;
#pragma unroll
        for (int t = 0; t < 9; t++) cp_async16(dst2 + tid + t * 256, src2 + tid + t * 256);
        asm volatile("cp.async.commit_group;\n");
    }

    // --- stage transposed weight matrices (overlaps with cp.async) ---
    for (int f = tid; f < Dm * Din; f += 256) {
        int i = f / Din, k = f - i * Din;
        sM1T[k * 97 + i] = M1[f];
        sWrT[k * 97 + i] = Wres1[f];
    }
    for (int f = tid; f < Dm * Dm; f += 256) {
        int i = f / Dm, k = f - i * Dm;
        sM2T[k * 97 + i] = M2[f];
    }
    for (int f = tid; f < Bsz * Din; f += 256) {
        int bb = f >> 6, k = f & 63;
        sx[f] = seq[((size_t)bb * S_TOTAL + s) * Din + k];
    }

    asm volatile("cp.async.wait_group 1;\n");   // W1 resident
    __syncthreads();

    const int i0 = lane, i1 = lane + 32, i2 = lane + 64;

    // ---- layer 1: xt = M1 x, res = Wres1 x ----
    float at0 = 0.f, at1 = 0.f, at2 = 0.f;
    float ar0 = 0.f, ar1 = 0.f, ar2 = 0.f;
    {
        const float* xr = sx + b * Din;
#pragma unroll 8
        for (int k = 0; k < Din; k++) {
            float xk = xr[k];
            const float* m = sM1T + k * 97;
            const float* r = sWrT + k * 97;
            at0 = fmaf(m[i0], xk, at0);
            at1 = fmaf(m[i1], xk, at1);
            at2 = fmaf(m[i2], xk, at2);
            ar0 = fmaf(r[i0], xk, ar0);
            ar1 = fmaf(r[i1], xk, ar1);
            ar2 = fmaf(r[i2], xk, ar2);
        }
    }
    // ---- LN 1 ----
    {
        float mu = warp_sum(at0 + at1 + at2) * (1.0f / 96.0f);
        float d0 = at0 - mu, d1 = at1 - mu, d2 = at2 - mu;
        float var = warp_sum(d0 * d0 + d1 * d1 + d2 * d2) * (1.0f / 96.0f);
        float rs = rsqrtf(var + 1e-5f);
        float* xo = sxn + b * Dm;
        xo[i0] = fmaf(d0 * rs, g1v[i0], b1v[i0]);
        xo[i1] = fmaf(d1 * rs, g1v[i1], b1v[i1]);
        xo[i2] = fmaf(d2 * rs, g1v[i2], b1v[i2]);
    }
    __syncwarp();

    // ---- Nk1 = W1[s] @ xn, + residual -> x1 ----
    float x10 = ar0, x11 = ar1, x12 = ar2;
    {
        const float* xr = sxn + b * Dm;
#pragma unroll 8
        for (int jj = 0; jj < Dm; jj++) {
            float xj = xr[jj];
            const float* w = sW1 + jj * Dm;
            x10 = fmaf(w[i0], xj, x10);
            x11 = fmaf(w[i1], xj, x11);
            x12 = fmaf(w[i2], xj, x12);
        }
    }
    {
        float* xo = sx1 + b * Dm;
        xo[i0] = x10;
        xo[i1] = x11;
        xo[i2] = x12;
    }
    asm volatile("cp.async.wait_group 0;\n");   // W2 resident
    __syncthreads();

    // ---- layer 2: xt2 = M2 x1 ----
    float t0 = 0.f, t1 = 0.f, t2 = 0.f;
    {
        const float* xr = sx1 + b * Dm;
#pragma unroll 8
        for (int k = 0; k < Dm; k++) {
            float xk = xr[k];
            const float* m = sM2T + k * 97;
            t0 = fmaf(m[i0], xk, t0);
            t1 = fmaf(m[i1], xk, t1);
            t2 = fmaf(m[i2], xk, t2);
        }
    }
    // ---- LN 2 ----
    {
        float mu = warp_sum(t0 + t1 + t2) * (1.0f / 96.0f);
        float d0 = t0 - mu, d1 = t1 - mu, d2 = t2 - mu;
        float var = warp_sum(d0 * d0 + d1 * d1 + d2 * d2) * (1.0f / 96.0f);
        float rs = rsqrtf(var + 1e-5f);
        float* xo = sxn + b * Dm;     // reuse (warp-private region)
        xo[i0] = fmaf(d0 * rs, g2v[i0], b2v[i0]);
        xo[i1] = fmaf(d1 * rs, g2v[i1], b2v[i1]);
        xo[i2] = fmaf(d2 * rs, g2v[i2], b2v[i2]);
    }
    __syncwarp();

    // ---- Nk2 = W2[s] @ xn2, + identity residual (x1 in regs) ----
    float o0 = x10, o1 = x11, o2 = x12;
    {
        const float* xr = sxn + b * Dm;
#pragma unroll 8
        for (int jj = 0; jj < Dm; jj++) {
            float xj = xr[jj];
            const float* w = sW2 + jj * Dm;
            o0 = fmaf(w[i0], xj, o0);
            o1 = fmaf(w[i1], xj, o1);
            o2 = fmaf(w[i2], xj, o2);
        }
    }
    float* op = out + ((size_t)b * S_TOTAL + s) * Dm;
    op[i0] = o0;
    op[i1] = o1;
    op[i2] = o2;
}

extern "C" void kernel_launch(void* const* d_in, const int* in_sizes, int n_in,
                              void* d_out, int out_size) {
    const float* seq = (const float*)d_in[0];
    const float* M1  = (const float*)d_in[1];
    const float* P1  = (const float*)d_in[2];
    const float* Wr1 = (const float*)d_in[3];
    const float* g1  = (const float*)d_in[4];
    const float* b1  = (const float*)d_in[5];
    const float* M2  = (const float*)d_in[6];
    const float* P2  = (const float*)d_in[7];
    const float* g2  = (const float*)d_in[8];
    const float* b2  = (const float*)d_in[9];
    float* out = (float*)d_out;

    cudaFuncSetAttribute(layers_kernel,
                         cudaFuncAttributeMaxDynamicSharedMemorySize, SMEM_BYTES);

    precompute_W<<<dim3(WELEM / 256, S_TOTAL / CHUNK, 2), 256>>>(P1, P2);
    layers_kernel<<<S_TOTAL, 256, SMEM_BYTES>>>(seq, M1, Wr1, g1, b1, M2, g2, b2, out);
}